// round 1
// baseline (speedup 1.0000x reference)
#include <cuda_runtime.h>
#include <cuda_bf16.h>

#define N_NODES 50000
#define N_EDGES 400000
#define E_TOT   (N_EDGES + N_NODES)
#define G_GRAPHS 256
#define HC 200
#define C_CH 100
#define SLOPE 0.2f

// ---------------- scratch (device globals; no allocation allowed) ------------
__device__ float g_h[(size_t)N_NODES * HC];      // linear output per layer
__device__ float g_x[(size_t)N_NODES * HC];      // activation (layer output)
__device__ float g_es[N_NODES * 2];
__device__ float g_ed[N_NODES * 2];
__device__ int   g_rowptr[N_NODES + 1];
__device__ int   g_cnt[N_NODES];
__device__ int   g_fill[N_NODES];
__device__ int   g_colsrc[E_TOT];
__device__ float g_pool[G_GRAPHS * HC];
__device__ int   g_gcnt[G_GRAPHS];

// ---------------- CSR build --------------------------------------------------
__global__ void k_init_counts() {
    int i = blockIdx.x * blockDim.x + threadIdx.x;
    if (i < N_NODES) { g_cnt[i] = 1; g_fill[i] = 1; }   // 1 = self-loop slot
}

__global__ void k_count(const int* __restrict__ ei) {
    int e = blockIdx.x * blockDim.x + threadIdx.x;
    if (e < N_EDGES) atomicAdd(&g_cnt[ei[N_EDGES + e]], 1);
}

// single-block chunked Hillis-Steele scan: rowptr[i+1] = incl_sum(cnt[0..i])
__global__ void k_scan() {
    __shared__ int sm[1024];
    __shared__ int carry;
    int tid = threadIdx.x;
    if (tid == 0) { carry = 0; g_rowptr[0] = 0; }
    __syncthreads();
    for (int base = 0; base < N_NODES; base += 1024) {
        int i = base + tid;
        int v = (i < N_NODES) ? g_cnt[i] : 0;
        sm[tid] = v;
        __syncthreads();
        for (int off = 1; off < 1024; off <<= 1) {
            int t = (tid >= off) ? sm[tid - off] : 0;
            __syncthreads();
            sm[tid] += t;
            __syncthreads();
        }
        if (i < N_NODES) g_rowptr[i + 1] = carry + sm[tid];
        __syncthreads();
        if (tid == 1023) carry += sm[1023];
        __syncthreads();
    }
}

__global__ void k_selfloop() {
    int i = blockIdx.x * blockDim.x + threadIdx.x;
    if (i < N_NODES) g_colsrc[g_rowptr[i]] = i;
}

__global__ void k_fill(const int* __restrict__ ei) {
    int e = blockIdx.x * blockDim.x + threadIdx.x;
    if (e < N_EDGES) {
        int d = ei[N_EDGES + e];
        int pos = g_rowptr[d] + atomicAdd(&g_fill[d], 1);
        g_colsrc[pos] = ei[e];
    }
}

__global__ void k_zero_pool() {
    int i = blockIdx.x * blockDim.x + threadIdx.x;
    if (i < G_GRAPHS * HC) g_pool[i] = 0.f;
    if (i < G_GRAPHS) g_gcnt[i] = 0;
}

// ---------------- SGEMM: C(g_h)[M x 200] = A[M x K] * B[K x 200] -------------
__global__ void k_sgemm(const float* __restrict__ Aext, int useExt,
                        const float* __restrict__ B, int M, int K) {
    const int BM = 128, BN = 128, BK = 8, TM = 8, TN = 8;
    const int Nn = HC;
    const float* A = useExt ? Aext : g_x;
    __shared__ float As[BK][BM];
    __shared__ float Bs[BK][BN];
    int tid = threadIdx.x;                  // 256 threads
    int tx = tid & 15, ty = tid >> 4;
    int rowBase = blockIdx.y * BM, colBase = blockIdx.x * BN;
    float acc[TM][TN];
#pragma unroll
    for (int i = 0; i < TM; i++)
#pragma unroll
        for (int j = 0; j < TN; j++) acc[i][j] = 0.f;

    int aRow = tid >> 1;
    int aK = (tid & 1) * 4;
    int bK = tid >> 5;
    int bCol = (tid & 31) * 4;

    for (int k0 = 0; k0 < K; k0 += BK) {
        float4 av = make_float4(0.f, 0.f, 0.f, 0.f);
        int gRow = rowBase + aRow;
        if (gRow < M) av = *(const float4*)(A + (size_t)gRow * K + k0 + aK);
        As[aK + 0][aRow] = av.x; As[aK + 1][aRow] = av.y;
        As[aK + 2][aRow] = av.z; As[aK + 3][aRow] = av.w;

        float4 bv = make_float4(0.f, 0.f, 0.f, 0.f);
        int gCol = colBase + bCol;
        if (gCol + 3 < Nn) {
            bv = *(const float4*)(B + (size_t)(k0 + bK) * Nn + gCol);
        } else {
            float t[4] = {0.f, 0.f, 0.f, 0.f};
#pragma unroll
            for (int j = 0; j < 4; j++)
                if (gCol + j < Nn) t[j] = B[(size_t)(k0 + bK) * Nn + gCol + j];
            bv = make_float4(t[0], t[1], t[2], t[3]);
        }
        Bs[bK][bCol + 0] = bv.x; Bs[bK][bCol + 1] = bv.y;
        Bs[bK][bCol + 2] = bv.z; Bs[bK][bCol + 3] = bv.w;
        __syncthreads();

#pragma unroll
        for (int kk = 0; kk < BK; kk++) {
            float ra[TM], rb[TN];
#pragma unroll
            for (int i = 0; i < TM; i++) ra[i] = As[kk][ty * TM + i];
#pragma unroll
            for (int j = 0; j < TN; j++) rb[j] = Bs[kk][tx * TN + j];
#pragma unroll
            for (int i = 0; i < TM; i++)
#pragma unroll
                for (int j = 0; j < TN; j++) acc[i][j] += ra[i] * rb[j];
        }
        __syncthreads();
    }

#pragma unroll
    for (int i = 0; i < TM; i++) {
        int r = rowBase + ty * TM + i;
        if (r < M) {
#pragma unroll
            for (int j = 0; j < TN; j++) {
                int c = colBase + tx * TN + j;
                if (c < Nn) g_h[(size_t)r * Nn + c] = acc[i][j];
            }
        }
    }
}

// ---------------- per-node attention scores ----------------------------------
__global__ void k_scores(const float* __restrict__ a_s, const float* __restrict__ a_d) {
    int gwarp = (blockIdx.x * blockDim.x + threadIdx.x) >> 5;
    int lane = threadIdx.x & 31;
    if (gwarp >= N_NODES) return;
    const float* hr = g_h + (size_t)gwarp * HC;
    float s0s = 0.f, s1s = 0.f, s0d = 0.f, s1d = 0.f;
#pragma unroll
    for (int k = 0; k < 7; k++) {
        int c = lane + 32 * k;
        if (c < HC) {
            float v = hr[c];
            float vs = v * a_s[c], vd = v * a_d[c];   // a is [H,C] flat = index c
            if (c < C_CH) { s0s += vs; s0d += vd; }
            else          { s1s += vs; s1d += vd; }
        }
    }
#pragma unroll
    for (int off = 16; off; off >>= 1) {
        s0s += __shfl_xor_sync(0xffffffffu, s0s, off);
        s1s += __shfl_xor_sync(0xffffffffu, s1s, off);
        s0d += __shfl_xor_sync(0xffffffffu, s0d, off);
        s1d += __shfl_xor_sync(0xffffffffu, s1d, off);
    }
    if (lane == 0) {
        g_es[gwarp * 2 + 0] = s0s; g_es[gwarp * 2 + 1] = s1s;
        g_ed[gwarp * 2 + 0] = s0d; g_ed[gwarp * 2 + 1] = s1d;
    }
}

__device__ __forceinline__ float lrelu(float v) { return v >= 0.f ? v : SLOPE * v; }

// ---------------- warp-per-dst softmax + aggregate + bias + relu -------------
__global__ void k_aggregate(const float* __restrict__ bias) {
    int n = (blockIdx.x * blockDim.x + threadIdx.x) >> 5;
    int lane = threadIdx.x & 31;
    if (n >= N_NODES) return;
    int beg = g_rowptr[n], end = g_rowptr[n + 1];
    float ed0 = g_ed[n * 2 + 0], ed1 = g_ed[n * 2 + 1];

    float m0 = -1e30f, m1 = -1e30f;
    for (int i = beg + lane; i < end; i += 32) {
        int s = g_colsrc[i];
        m0 = fmaxf(m0, lrelu(g_es[s * 2 + 0] + ed0));
        m1 = fmaxf(m1, lrelu(g_es[s * 2 + 1] + ed1));
    }
#pragma unroll
    for (int off = 16; off; off >>= 1) {
        m0 = fmaxf(m0, __shfl_xor_sync(0xffffffffu, m0, off));
        m1 = fmaxf(m1, __shfl_xor_sync(0xffffffffu, m1, off));
    }

    float s0 = 0.f, s1 = 0.f;
    for (int i = beg + lane; i < end; i += 32) {
        int s = g_colsrc[i];
        s0 += __expf(lrelu(g_es[s * 2 + 0] + ed0) - m0);
        s1 += __expf(lrelu(g_es[s * 2 + 1] + ed1) - m1);
    }
#pragma unroll
    for (int off = 16; off; off >>= 1) {
        s0 += __shfl_xor_sync(0xffffffffu, s0, off);
        s1 += __shfl_xor_sync(0xffffffffu, s1, off);
    }
    float inv0 = 1.f / (s0 + 1e-16f), inv1 = 1.f / (s1 + 1e-16f);

    float acc[7];
#pragma unroll
    for (int k = 0; k < 7; k++) acc[k] = 0.f;

    for (int i = beg; i < end; i++) {              // whole warp per edge
        int s = g_colsrc[i];
        float a0 = __expf(lrelu(g_es[s * 2 + 0] + ed0) - m0) * inv0;
        float a1 = __expf(lrelu(g_es[s * 2 + 1] + ed1) - m1) * inv1;
        const float* hr = g_h + (size_t)s * HC;
#pragma unroll
        for (int k = 0; k < 7; k++) {
            int c = lane + 32 * k;
            if (c < HC) acc[k] += (c < C_CH ? a0 : a1) * hr[c];
        }
    }
#pragma unroll
    for (int k = 0; k < 7; k++) {
        int c = lane + 32 * k;
        if (c < HC) {
            float v = acc[k] + bias[c];
            g_x[(size_t)n * HC + c] = v > 0.f ? v : 0.f;   // relu
        }
    }
}

// ---------------- global mean pool -------------------------------------------
__global__ void k_pool(const int* __restrict__ batch) {
    int n = (blockIdx.x * blockDim.x + threadIdx.x) >> 5;
    int lane = threadIdx.x & 31;
    if (n >= N_NODES) return;
    int g = batch[n];
#pragma unroll
    for (int k = 0; k < 7; k++) {
        int c = lane + 32 * k;
        if (c < HC) atomicAdd(&g_pool[g * HC + c], g_x[(size_t)n * HC + c]);
    }
    if (lane == 0) atomicAdd(&g_gcnt[g], 1);
}

// ---------------- fused MLP head ---------------------------------------------
__global__ void k_mlp(const float* __restrict__ lw1, const float* __restrict__ lb1,
                      const float* __restrict__ lw2, const float* __restrict__ lb2,
                      const float* __restrict__ lw3, const float* __restrict__ lb3,
                      float* __restrict__ out) {
    int g = blockIdx.x;
    int t = threadIdx.x;     // 128
    __shared__ float buf[HC];
    __shared__ float t1[100];
    __shared__ float t2[100];
    float inv = 1.f / fmaxf((float)g_gcnt[g], 1.f);
    for (int k = t; k < HC; k += blockDim.x) buf[k] = g_pool[g * HC + k] * inv;
    __syncthreads();
    if (t < 100) {
        float s = lb1[t];
        for (int k = 0; k < HC; k++) s += buf[k] * lw1[k * 100 + t];
        t1[t] = fmaxf(s, 0.f);
    }
    __syncthreads();
    if (t < 100) {
        float s = lb2[t];
        for (int k = 0; k < 100; k++) s += t1[k] * lw2[k * 100 + t];
        t2[t] = fmaxf(s, 0.f);
    }
    __syncthreads();
    if (t < 29) {
        float s = lb3[t];
        for (int k = 0; k < 100; k++) s += t2[k] * lw3[k * 29 + t];
        out[g * 29 + t] = s;
    }
}

// ---------------- launch ------------------------------------------------------
extern "C" void kernel_launch(void* const* d_in, const int* in_sizes, int n_in,
                              void* d_out, int out_size) {
    const float* x     = (const float*)d_in[0];
    const int*   ei    = (const int*)d_in[1];
    const int*   batch = (const int*)d_in[2];
    const float* W[5];
    const float* Asr[5];
    const float* Ads[5];
    const float* Bc[5];
    for (int i = 0; i < 5; i++) {
        W[i]   = (const float*)d_in[3 + 4 * i];
        Asr[i] = (const float*)d_in[4 + 4 * i];
        Ads[i] = (const float*)d_in[5 + 4 * i];
        Bc[i]  = (const float*)d_in[6 + 4 * i];
    }
    const float* lw1 = (const float*)d_in[23];
    const float* lb1 = (const float*)d_in[24];
    const float* lw2 = (const float*)d_in[25];
    const float* lb2 = (const float*)d_in[26];
    const float* lw3 = (const float*)d_in[27];
    const float* lb3 = (const float*)d_in[28];
    float* out = (float*)d_out;

    // CSR (edges fixed but rebuilt every launch for determinism rules)
    k_init_counts<<<(N_NODES + 255) / 256, 256>>>();
    k_count<<<(N_EDGES + 255) / 256, 256>>>(ei);
    k_scan<<<1, 1024>>>();
    k_selfloop<<<(N_NODES + 255) / 256, 256>>>();
    k_fill<<<(N_EDGES + 255) / 256, 256>>>(ei);
    k_zero_pool<<<(G_GRAPHS * HC + 255) / 256, 256>>>();

    dim3 gemmGrid((HC + 127) / 128, (N_NODES + 127) / 128);
    int Kdims[5] = {336, 200, 200, 200, 200};
    int wblocks = (N_NODES + 7) / 8;   // 8 warps / 256-thread block
    for (int L = 0; L < 5; L++) {
        k_sgemm<<<gemmGrid, 256>>>(x, L == 0 ? 1 : 0, W[L], N_NODES, Kdims[L]);
        k_scores<<<wblocks, 256>>>(Asr[L], Ads[L]);
        k_aggregate<<<wblocks, 256>>>(Bc[L]);
    }
    k_pool<<<wblocks, 256>>>(batch);
    k_mlp<<<G_GRAPHS, 128>>>(lw1, lb1, lw2, lb2, lw3, lb3, out);
}

// round 2
// speedup vs baseline: 1.1478x; 1.1478x over previous
#include <cuda_runtime.h>
#include <cuda_bf16.h>
#include <cstdint>

#define N_NODES 50000
#define N_EDGES 400000
#define E_TOT   (N_EDGES + N_NODES)
#define G_GRAPHS 256
#define HC 200
#define C_CH 100
#define SLOPE 0.2f

// ---------------- scratch (device globals; no allocation allowed) ------------
__device__ float g_h[(size_t)N_NODES * HC];      // linear output per layer
__device__ float g_x[(size_t)N_NODES * HC];      // activation (layer output)
__device__ float g_es[N_NODES * 2];
__device__ float g_ed[N_NODES * 2];
__device__ int   g_rowptr[N_NODES + 1];
__device__ int   g_cnt[N_NODES];
__device__ int   g_fill[N_NODES];
__device__ int   g_colsrc[E_TOT];
__device__ float g_pool[G_GRAPHS * HC];

// ---------------- CSR build --------------------------------------------------
__global__ void k_init_counts() {
    int i = blockIdx.x * blockDim.x + threadIdx.x;
    if (i < N_NODES) { g_cnt[i] = 1; g_fill[i] = 1; }   // 1 = self-loop slot
}

__global__ void k_count(const int* __restrict__ ei) {
    int e = blockIdx.x * blockDim.x + threadIdx.x;
    if (e < N_EDGES) atomicAdd(&g_cnt[ei[N_EDGES + e]], 1);
}

// single-block chunked Hillis-Steele scan: rowptr[i+1] = incl_sum(cnt[0..i])
__global__ void k_scan() {
    __shared__ int sm[1024];
    __shared__ int carry;
    int tid = threadIdx.x;
    if (tid == 0) { carry = 0; g_rowptr[0] = 0; }
    __syncthreads();
    for (int base = 0; base < N_NODES; base += 1024) {
        int i = base + tid;
        int v = (i < N_NODES) ? g_cnt[i] : 0;
        sm[tid] = v;
        __syncthreads();
        for (int off = 1; off < 1024; off <<= 1) {
            int t = (tid >= off) ? sm[tid - off] : 0;
            __syncthreads();
            sm[tid] += t;
            __syncthreads();
        }
        if (i < N_NODES) g_rowptr[i + 1] = carry + sm[tid];
        __syncthreads();
        if (tid == 1023) carry += sm[1023];
        __syncthreads();
    }
}

__global__ void k_selfloop() {
    int i = blockIdx.x * blockDim.x + threadIdx.x;
    if (i < N_NODES) g_colsrc[g_rowptr[i]] = i;
}

__global__ void k_fill(const int* __restrict__ ei) {
    int e = blockIdx.x * blockDim.x + threadIdx.x;
    if (e < N_EDGES) {
        int d = ei[N_EDGES + e];
        int pos = g_rowptr[d] + atomicAdd(&g_fill[d], 1);
        g_colsrc[pos] = ei[e];
    }
}

// ---------------- TF32 helpers -----------------------------------------------
__device__ __forceinline__ float tf32_rna(float x) {
    uint32_t u;
    asm("cvt.rna.tf32.f32 %0, %1;" : "=r"(u) : "f"(x));
    return __uint_as_float(u);
}

__device__ __forceinline__ void mma_tf32(float& c0, float& c1, float& c2, float& c3,
                                         float a0, float a1, float a2, float a3,
                                         float b0, float b1) {
    asm volatile(
        "mma.sync.aligned.m16n8k8.row.col.f32.tf32.tf32.f32 "
        "{%0,%1,%2,%3},{%4,%5,%6,%7},{%8,%9},{%0,%1,%2,%3};"
        : "+f"(c0), "+f"(c1), "+f"(c2), "+f"(c3)
        : "r"(__float_as_uint(a0)), "r"(__float_as_uint(a1)),
          "r"(__float_as_uint(a2)), "r"(__float_as_uint(a3)),
          "r"(__float_as_uint(b0)), "r"(__float_as_uint(b1)));
}

// ---------------- tensor-core GEMM: g_h[M x 200] = A[M x K] * B[K x 200] -----
// 3xTF32 split for ~fp32 accuracy. Block 128x64, 8 warps (4M x 2N),
// warp tile 32x32 -> 2x4 m16n8k8 mma tiles.
#define BM 128
#define BN 64
#define BK 16
#define A_STRIDE 20   // conflict-free for A-fragment access pattern
#define B_STRIDE 72   // conflict-free for B-fragment access pattern

__global__ void __launch_bounds__(256)
k_gemm_tf32(const float* __restrict__ Aext, int useExt,
            const float* __restrict__ B, int M, int K) {
    __shared__ float As_h[BM][A_STRIDE];
    __shared__ float As_l[BM][A_STRIDE];
    __shared__ float Bs_h[BK][B_STRIDE];
    __shared__ float Bs_l[BK][B_STRIDE];

    const float* A = useExt ? Aext : g_x;
    int tid = threadIdx.x;
    int lane = tid & 31, warp = tid >> 5;
    int wm = warp & 3, wn = warp >> 2;           // warp grid 4x2
    int rowW = wm * 32, colW = wn * 32;          // warp tile origin in block
    int rowBase = blockIdx.y * BM, colBase = blockIdx.x * BN;
    int groupr = lane >> 2, kc = lane & 3;

    float acc[2][4][4];
#pragma unroll
    for (int mi = 0; mi < 2; mi++)
#pragma unroll
        for (int ni = 0; ni < 4; ni++)
#pragma unroll
            for (int r = 0; r < 4; r++) acc[mi][ni][r] = 0.f;

    // staging index precompute
    int aRow = tid >> 1;                 // 0..127
    int aK = (tid & 1) * 8;              // 0 or 8
    int bK = tid >> 4;                   // 0..15
    int bCol = (tid & 15) * 4;           // 0..60

    for (int k0 = 0; k0 < K; k0 += BK) {
        // ---- stage A (128x16) ----
        {
            int gRow = rowBase + aRow;
            const float* ap = A + (size_t)gRow * K + k0 + aK;
#pragma unroll
            for (int v = 0; v < 2; v++) {
                int kg = k0 + aK + v * 4;
                float4 f = make_float4(0.f, 0.f, 0.f, 0.f);
                if (gRow < M && kg < K) f = *(const float4*)(ap + v * 4);
                float vals[4] = {f.x, f.y, f.z, f.w};
#pragma unroll
                for (int j = 0; j < 4; j++) {
                    float hi = tf32_rna(vals[j]);
                    As_h[aRow][aK + v * 4 + j] = hi;
                    As_l[aRow][aK + v * 4 + j] = tf32_rna(vals[j] - hi);
                }
            }
        }
        // ---- stage B (16x64) ----
        {
            int gK = k0 + bK;
            int gCol = colBase + bCol;
            float4 f = make_float4(0.f, 0.f, 0.f, 0.f);
            if (gK < K && gCol + 3 < HC)
                f = *(const float4*)(B + (size_t)gK * HC + gCol);
            else if (gK < K) {
                float t[4] = {0.f, 0.f, 0.f, 0.f};
#pragma unroll
                for (int j = 0; j < 4; j++)
                    if (gCol + j < HC) t[j] = B[(size_t)gK * HC + gCol + j];
                f = make_float4(t[0], t[1], t[2], t[3]);
            }
            float vals[4] = {f.x, f.y, f.z, f.w};
#pragma unroll
            for (int j = 0; j < 4; j++) {
                float hi = tf32_rna(vals[j]);
                Bs_h[bK][bCol + j] = hi;
                Bs_l[bK][bCol + j] = tf32_rna(vals[j] - hi);
            }
        }
        __syncthreads();

#pragma unroll
        for (int kk = 0; kk < BK; kk += 8) {
            // A fragments (hi+lo) for both m-tiles
            float ah[2][4], al[2][4];
#pragma unroll
            for (int mi = 0; mi < 2; mi++) {
                int r0 = rowW + mi * 16 + groupr;
                ah[mi][0] = As_h[r0][kk + kc];
                ah[mi][1] = As_h[r0 + 8][kk + kc];
                ah[mi][2] = As_h[r0][kk + kc + 4];
                ah[mi][3] = As_h[r0 + 8][kk + kc + 4];
                al[mi][0] = As_l[r0][kk + kc];
                al[mi][1] = As_l[r0 + 8][kk + kc];
                al[mi][2] = As_l[r0][kk + kc + 4];
                al[mi][3] = As_l[r0 + 8][kk + kc + 4];
            }
            // B fragments (hi+lo) for 4 n-tiles
            float bh[4][2], bl[4][2];
#pragma unroll
            for (int ni = 0; ni < 4; ni++) {
                int c0 = colW + ni * 8 + groupr;
                bh[ni][0] = Bs_h[kk + kc][c0];
                bh[ni][1] = Bs_h[kk + kc + 4][c0];
                bl[ni][0] = Bs_l[kk + kc][c0];
                bl[ni][1] = Bs_l[kk + kc + 4][c0];
            }
#pragma unroll
            for (int mi = 0; mi < 2; mi++)
#pragma unroll
                for (int ni = 0; ni < 4; ni++) {
                    float* c = acc[mi][ni];
                    mma_tf32(c[0], c[1], c[2], c[3],
                             ah[mi][0], ah[mi][1], ah[mi][2], ah[mi][3],
                             bh[ni][0], bh[ni][1]);
                    mma_tf32(c[0], c[1], c[2], c[3],
                             al[mi][0], al[mi][1], al[mi][2], al[mi][3],
                             bh[ni][0], bh[ni][1]);
                    mma_tf32(c[0], c[1], c[2], c[3],
                             ah[mi][0], ah[mi][1], ah[mi][2], ah[mi][3],
                             bl[ni][0], bl[ni][1]);
                }
        }
        __syncthreads();
    }

    // epilogue
#pragma unroll
    for (int mi = 0; mi < 2; mi++) {
#pragma unroll
        for (int ni = 0; ni < 4; ni++) {
            int r = rowBase + rowW + mi * 16 + groupr;
            int c = colBase + colW + ni * 8 + kc * 2;
            if (r < M) {
                if (c < HC)     g_h[(size_t)r * HC + c]     = acc[mi][ni][0];
                if (c + 1 < HC) g_h[(size_t)r * HC + c + 1] = acc[mi][ni][1];
            }
            if (r + 8 < M) {
                if (c < HC)     g_h[(size_t)(r + 8) * HC + c]     = acc[mi][ni][2];
                if (c + 1 < HC) g_h[(size_t)(r + 8) * HC + c + 1] = acc[mi][ni][3];
            }
        }
    }
}

// ---------------- per-node attention scores ----------------------------------
__global__ void k_scores(const float* __restrict__ a_s, const float* __restrict__ a_d) {
    int gwarp = (blockIdx.x * blockDim.x + threadIdx.x) >> 5;
    int lane = threadIdx.x & 31;
    if (gwarp >= N_NODES) return;
    const float* hr = g_h + (size_t)gwarp * HC;
    float s0s = 0.f, s1s = 0.f, s0d = 0.f, s1d = 0.f;
#pragma unroll
    for (int k = 0; k < 7; k++) {
        int c = lane + 32 * k;
        if (c < HC) {
            float v = hr[c];
            float vs = v * a_s[c], vd = v * a_d[c];
            if (c < C_CH) { s0s += vs; s0d += vd; }
            else          { s1s += vs; s1d += vd; }
        }
    }
#pragma unroll
    for (int off = 16; off; off >>= 1) {
        s0s += __shfl_xor_sync(0xffffffffu, s0s, off);
        s1s += __shfl_xor_sync(0xffffffffu, s1s, off);
        s0d += __shfl_xor_sync(0xffffffffu, s0d, off);
        s1d += __shfl_xor_sync(0xffffffffu, s1d, off);
    }
    if (lane == 0) {
        g_es[gwarp * 2 + 0] = s0s; g_es[gwarp * 2 + 1] = s1s;
        g_ed[gwarp * 2 + 0] = s0d; g_ed[gwarp * 2 + 1] = s1d;
    }
}

__device__ __forceinline__ float lrelu(float v) { return v >= 0.f ? v : SLOPE * v; }

// ---------------- warp-per-dst softmax + aggregate + bias + relu -------------
__global__ void k_aggregate(const float* __restrict__ bias) {
    int n = (blockIdx.x * blockDim.x + threadIdx.x) >> 5;
    int lane = threadIdx.x & 31;
    if (n >= N_NODES) return;
    int beg = g_rowptr[n], end = g_rowptr[n + 1];
    float ed0 = g_ed[n * 2 + 0], ed1 = g_ed[n * 2 + 1];

    float m0 = -1e30f, m1 = -1e30f;
    for (int i = beg + lane; i < end; i += 32) {
        int s = g_colsrc[i];
        m0 = fmaxf(m0, lrelu(g_es[s * 2 + 0] + ed0));
        m1 = fmaxf(m1, lrelu(g_es[s * 2 + 1] + ed1));
    }
#pragma unroll
    for (int off = 16; off; off >>= 1) {
        m0 = fmaxf(m0, __shfl_xor_sync(0xffffffffu, m0, off));
        m1 = fmaxf(m1, __shfl_xor_sync(0xffffffffu, m1, off));
    }

    float s0 = 0.f, s1 = 0.f;
    for (int i = beg + lane; i < end; i += 32) {
        int s = g_colsrc[i];
        s0 += __expf(lrelu(g_es[s * 2 + 0] + ed0) - m0);
        s1 += __expf(lrelu(g_es[s * 2 + 1] + ed1) - m1);
    }
#pragma unroll
    for (int off = 16; off; off >>= 1) {
        s0 += __shfl_xor_sync(0xffffffffu, s0, off);
        s1 += __shfl_xor_sync(0xffffffffu, s1, off);
    }
    float inv0 = 1.f / (s0 + 1e-16f), inv1 = 1.f / (s1 + 1e-16f);

    float acc[7];
#pragma unroll
    for (int k = 0; k < 7; k++) acc[k] = 0.f;

    for (int i = beg; i < end; i++) {              // whole warp per edge
        int s = g_colsrc[i];
        float a0 = __expf(lrelu(g_es[s * 2 + 0] + ed0) - m0) * inv0;
        float a1 = __expf(lrelu(g_es[s * 2 + 1] + ed1) - m1) * inv1;
        const float* hr = g_h + (size_t)s * HC;
#pragma unroll
        for (int k = 0; k < 7; k++) {
            int c = lane + 32 * k;
            if (c < HC) acc[k] += (c < C_CH ? a0 : a1) * hr[c];
        }
    }
#pragma unroll
    for (int k = 0; k < 7; k++) {
        int c = lane + 32 * k;
        if (c < HC) {
            float v = acc[k] + bias[c];
            g_x[(size_t)n * HC + c] = v > 0.f ? v : 0.f;   // relu
        }
    }
}

// ---------------- global mean pool (batch is sorted -> segment reduce) -------
__global__ void k_pool_seg(const int* __restrict__ batch) {
    int g = blockIdx.x;
    int t = threadIdx.x;    // 256

    // lower_bound(g) and lower_bound(g+1)
    int lo = 0, hi = N_NODES;
    while (lo < hi) { int m = (lo + hi) >> 1; if (batch[m] < g) lo = m + 1; else hi = m; }
    int beg = lo;
    hi = N_NODES;
    while (lo < hi) { int m = (lo + hi) >> 1; if (batch[m] < g + 1) lo = m + 1; else hi = m; }
    int end = lo;
    int cnt = end - beg;
    float inv = 1.f / fmaxf((float)cnt, 1.f);

    for (int c = t; c < HC; c += blockDim.x) {
        float s = 0.f;
        for (int n = beg; n < end; n++) s += g_x[(size_t)n * HC + c];
        g_pool[g * HC + c] = s * inv;
    }
}

// ---------------- fused MLP head ---------------------------------------------
__global__ void k_mlp(const float* __restrict__ lw1, const float* __restrict__ lb1,
                      const float* __restrict__ lw2, const float* __restrict__ lb2,
                      const float* __restrict__ lw3, const float* __restrict__ lb3,
                      float* __restrict__ out) {
    int g = blockIdx.x;
    int t = threadIdx.x;     // 128
    __shared__ float buf[HC];
    __shared__ float t1[100];
    __shared__ float t2[100];
    for (int k = t; k < HC; k += blockDim.x) buf[k] = g_pool[g * HC + k];
    __syncthreads();
    if (t < 100) {
        float s = lb1[t];
        for (int k = 0; k < HC; k++) s += buf[k] * lw1[k * 100 + t];
        t1[t] = fmaxf(s, 0.f);
    }
    __syncthreads();
    if (t < 100) {
        float s = lb2[t];
        for (int k = 0; k < 100; k++) s += t1[k] * lw2[k * 100 + t];
        t2[t] = fmaxf(s, 0.f);
    }
    __syncthreads();
    if (t < 29) {
        float s = lb3[t];
        for (int k = 0; k < 100; k++) s += t2[k] * lw3[k * 29 + t];
        out[g * 29 + t] = s;
    }
}

// ---------------- launch ------------------------------------------------------
extern "C" void kernel_launch(void* const* d_in, const int* in_sizes, int n_in,
                              void* d_out, int out_size) {
    const float* x     = (const float*)d_in[0];
    const int*   ei    = (const int*)d_in[1];
    const int*   batch = (const int*)d_in[2];
    const float* W[5];
    const float* Asr[5];
    const float* Ads[5];
    const float* Bc[5];
    for (int i = 0; i < 5; i++) {
        W[i]   = (const float*)d_in[3 + 4 * i];
        Asr[i] = (const float*)d_in[4 + 4 * i];
        Ads[i] = (const float*)d_in[5 + 4 * i];
        Bc[i]  = (const float*)d_in[6 + 4 * i];
    }
    const float* lw1 = (const float*)d_in[23];
    const float* lb1 = (const float*)d_in[24];
    const float* lw2 = (const float*)d_in[25];
    const float* lb2 = (const float*)d_in[26];
    const float* lw3 = (const float*)d_in[27];
    const float* lb3 = (const float*)d_in[28];
    float* out = (float*)d_out;

    k_init_counts<<<(N_NODES + 255) / 256, 256>>>();
    k_count<<<(N_EDGES + 255) / 256, 256>>>(ei);
    k_scan<<<1, 1024>>>();
    k_selfloop<<<(N_NODES + 255) / 256, 256>>>();
    k_fill<<<(N_EDGES + 255) / 256, 256>>>(ei);

    dim3 gemmGrid((HC + BN - 1) / BN, (N_NODES + BM - 1) / BM);
    int Kdims[5] = {336, 200, 200, 200, 200};
    int wblocks = (N_NODES + 7) / 8;   // 8 warps / 256-thread block
    for (int L = 0; L < 5; L++) {
        k_gemm_tf32<<<gemmGrid, 256>>>(x, L == 0 ? 1 : 0, W[L], N_NODES, Kdims[L]);
        k_scores<<<wblocks, 256>>>(Asr[L], Ads[L]);
        k_aggregate<<<wblocks, 256>>>(Bc[L]);
    }
    k_pool_seg<<<G_GRAPHS, 256>>>(batch);
    k_mlp<<<G_GRAPHS, 128>>>(lw1, lb1, lw2, lb2, lw3, lb3, out);
}

// round 3
// speedup vs baseline: 1.2891x; 1.1231x over previous
#include <cuda_runtime.h>
#include <cuda_bf16.h>
#include <cstdint>

#define N_NODES 50000
#define N_EDGES 400000
#define E_TOT   (N_EDGES + N_NODES)
#define G_GRAPHS 256
#define HC 200
#define C_CH 100
#define SLOPE 0.2f

#define TM_TILES 3125          // 50000 / 16
#define TN_TILES 25            // 200 / 8
#define KS_MAX 42              // 336 / 8

// ---------------- scratch (device globals; no allocation allowed) ------------
__device__ float g_h[(size_t)N_NODES * HC];
__device__ float g_x[(size_t)N_NODES * HC];
__device__ float g_es[N_NODES * 2];
__device__ float g_ed[N_NODES * 2];
__device__ int   g_rowptr[N_NODES + 1];
__device__ int   g_cnt[N_NODES];
__device__ int   g_fill[N_NODES];
__device__ int   g_colsrc[E_TOT];
__device__ float g_pool[G_GRAPHS * HC];
// permuted, tf32-split operands (fragment order)
__device__ float g_pah[(size_t)TM_TILES * KS_MAX * 32 * 4];
__device__ float g_pal[(size_t)TM_TILES * KS_MAX * 32 * 4];
__device__ float g_pbh[(size_t)TN_TILES * KS_MAX * 32 * 2];
__device__ float g_pbl[(size_t)TN_TILES * KS_MAX * 32 * 2];

// ---------------- CSR build --------------------------------------------------
__global__ void k_init_counts() {
    int i = blockIdx.x * blockDim.x + threadIdx.x;
    if (i < N_NODES) { g_cnt[i] = 1; g_fill[i] = 1; }
}

__global__ void k_count(const int* __restrict__ ei) {
    int e = blockIdx.x * blockDim.x + threadIdx.x;
    if (e < N_EDGES) atomicAdd(&g_cnt[ei[N_EDGES + e]], 1);
}

__global__ void k_scan() {
    __shared__ int sm[1024];
    __shared__ int carry;
    int tid = threadIdx.x;
    if (tid == 0) { carry = 0; g_rowptr[0] = 0; }
    __syncthreads();
    for (int base = 0; base < N_NODES; base += 1024) {
        int i = base + tid;
        int v = (i < N_NODES) ? g_cnt[i] : 0;
        sm[tid] = v;
        __syncthreads();
        for (int off = 1; off < 1024; off <<= 1) {
            int t = (tid >= off) ? sm[tid - off] : 0;
            __syncthreads();
            sm[tid] += t;
            __syncthreads();
        }
        if (i < N_NODES) g_rowptr[i + 1] = carry + sm[tid];
        __syncthreads();
        if (tid == 1023) carry += sm[1023];
        __syncthreads();
    }
}

__global__ void k_selfloop() {
    int i = blockIdx.x * blockDim.x + threadIdx.x;
    if (i < N_NODES) g_colsrc[g_rowptr[i]] = i;
}

__global__ void k_fill(const int* __restrict__ ei) {
    int e = blockIdx.x * blockDim.x + threadIdx.x;
    if (e < N_EDGES) {
        int d = ei[N_EDGES + e];
        int pos = g_rowptr[d] + atomicAdd(&g_fill[d], 1);
        g_colsrc[pos] = ei[e];
    }
}

// ---------------- TF32 helpers -----------------------------------------------
__device__ __forceinline__ float tf32_rna(float x) {
    uint32_t u;
    asm("cvt.rna.tf32.f32 %0, %1;" : "=r"(u) : "f"(x));
    return __uint_as_float(u);
}

__device__ __forceinline__ void mma_tf32(float& c0, float& c1, float& c2, float& c3,
                                         float a0, float a1, float a2, float a3,
                                         float b0, float b1) {
    asm volatile(
        "mma.sync.aligned.m16n8k8.row.col.f32.tf32.tf32.f32 "
        "{%0,%1,%2,%3},{%4,%5,%6,%7},{%8,%9},{%0,%1,%2,%3};"
        : "+f"(c0), "+f"(c1), "+f"(c2), "+f"(c3)
        : "r"(__float_as_uint(a0)), "r"(__float_as_uint(a1)),
          "r"(__float_as_uint(a2)), "r"(__float_as_uint(a3)),
          "r"(__float_as_uint(b0)), "r"(__float_as_uint(b1)));
}

// ---------------- operand pre-permute + hi/lo split --------------------------
// PA[tm][ks][lane][j]: j0=(groupr,kc) j1=(groupr+8,kc) j2=(groupr,kc+4) j3=(groupr+8,kc+4)
__global__ void k_convA(const float* __restrict__ A, int K, int KS, int total) {
    int t = blockIdx.x * blockDim.x + threadIdx.x;
    if (t >= total) return;
    int lane = t & 31;
    int rest = t >> 5;
    int ks = rest % KS;
    int tm = rest / KS;
    int groupr = lane >> 2, kc = lane & 3;
    int r0 = tm * 16 + groupr, r1 = r0 + 8;
    int k0 = ks * 8 + kc, k1 = k0 + 4;
    float v0 = A[(size_t)r0 * K + k0];
    float v1 = A[(size_t)r1 * K + k0];
    float v2 = A[(size_t)r0 * K + k1];
    float v3 = A[(size_t)r1 * K + k1];
    float h0 = tf32_rna(v0), h1 = tf32_rna(v1), h2 = tf32_rna(v2), h3 = tf32_rna(v3);
    ((float4*)g_pah)[t] = make_float4(h0, h1, h2, h3);
    ((float4*)g_pal)[t] = make_float4(tf32_rna(v0 - h0), tf32_rna(v1 - h1),
                                      tf32_rna(v2 - h2), tf32_rna(v3 - h3));
}

// PB[tn][ks][lane][j]: j0=(k=kc, n=tn*8+groupr) j1=(k=kc+4, same n);  B is [K][200]
__global__ void k_convB(const float* __restrict__ B, int K, int KS, int total) {
    int t = blockIdx.x * blockDim.x + threadIdx.x;
    if (t >= total) return;
    int lane = t & 31;
    int rest = t >> 5;
    int ks = rest % KS;
    int tn = rest / KS;
    int groupr = lane >> 2, kc = lane & 3;
    int n = tn * 8 + groupr;
    int k0 = ks * 8 + kc, k1 = k0 + 4;
    float v0 = B[(size_t)k0 * HC + n];
    float v1 = B[(size_t)k1 * HC + n];
    float h0 = tf32_rna(v0), h1 = tf32_rna(v1);
    ((float2*)g_pbh)[t] = make_float2(h0, h1);
    ((float2*)g_pbl)[t] = make_float2(tf32_rna(v0 - h0), tf32_rna(v1 - h1));
}

// ---------------- smem-free tensor-core GEMM ---------------------------------
// block = 8 warps (4m x 2n), warp tile 32x32, block tile 128x64.
__global__ void __launch_bounds__(256)
k_gemm_tc(int KS) {
    int tid = threadIdx.x;
    int lane = tid & 31, warp = tid >> 5;
    int wm = warp & 3, wn = warp >> 2;
    int tm0 = blockIdx.y * 8 + wm * 2;           // two m-tiles: tm0, tm0+1
    int tnB = blockIdx.x * 8 + wn * 4;           // four n-tiles
    if (tnB >= TN_TILES) return;                 // fully out-of-range warp

    const float4* pah = (const float4*)g_pah;
    const float4* pal = (const float4*)g_pal;
    const float2* pbh = (const float2*)g_pbh;
    const float2* pbl = (const float2*)g_pbl;

    bool mv0 = tm0 < TM_TILES;
    bool mv1 = (tm0 + 1) < TM_TILES;
    bool nv[4];
#pragma unroll
    for (int ni = 0; ni < 4; ni++) nv[ni] = (tnB + ni) < TN_TILES;

    size_t aBase0 = ((size_t)tm0 * KS) * 32 + lane;
    size_t aBase1 = aBase0 + (size_t)KS * 32;
    size_t bBase[4];
#pragma unroll
    for (int ni = 0; ni < 4; ni++) bBase[ni] = ((size_t)(tnB + ni) * KS) * 32 + lane;

    float acc[2][4][4];
#pragma unroll
    for (int mi = 0; mi < 2; mi++)
#pragma unroll
        for (int ni = 0; ni < 4; ni++)
#pragma unroll
            for (int r = 0; r < 4; r++) acc[mi][ni][r] = 0.f;

    const float4 z4 = make_float4(0.f, 0.f, 0.f, 0.f);
    const float2 z2 = make_float2(0.f, 0.f);

#pragma unroll 2
    for (int ks = 0; ks < KS; ks++) {
        size_t off = (size_t)ks * 32;
        float4 ah0 = mv0 ? pah[aBase0 + off] : z4;
        float4 al0 = mv0 ? pal[aBase0 + off] : z4;
        float4 ah1 = mv1 ? pah[aBase1 + off] : z4;
        float4 al1 = mv1 ? pal[aBase1 + off] : z4;
        float2 bh[4], bl[4];
#pragma unroll
        for (int ni = 0; ni < 4; ni++) {
            bh[ni] = nv[ni] ? pbh[bBase[ni] + off] : z2;
            bl[ni] = nv[ni] ? pbl[bBase[ni] + off] : z2;
        }
#pragma unroll
        for (int ni = 0; ni < 4; ni++) {
            {
                float* c = acc[0][ni];
                mma_tf32(c[0], c[1], c[2], c[3], ah0.x, ah0.y, ah0.z, ah0.w, bh[ni].x, bh[ni].y);
                mma_tf32(c[0], c[1], c[2], c[3], al0.x, al0.y, al0.z, al0.w, bh[ni].x, bh[ni].y);
                mma_tf32(c[0], c[1], c[2], c[3], ah0.x, ah0.y, ah0.z, ah0.w, bl[ni].x, bl[ni].y);
            }
            {
                float* c = acc[1][ni];
                mma_tf32(c[0], c[1], c[2], c[3], ah1.x, ah1.y, ah1.z, ah1.w, bh[ni].x, bh[ni].y);
                mma_tf32(c[0], c[1], c[2], c[3], al1.x, al1.y, al1.z, al1.w, bh[ni].x, bh[ni].y);
                mma_tf32(c[0], c[1], c[2], c[3], ah1.x, ah1.y, ah1.z, ah1.w, bl[ni].x, bl[ni].y);
            }
        }
    }

    int groupr = lane >> 2, kc = lane & 3;
#pragma unroll
    for (int mi = 0; mi < 2; mi++) {
        int r = (tm0 + mi) * 16 + groupr;
#pragma unroll
        for (int ni = 0; ni < 4; ni++) {
            int c = (tnB + ni) * 8 + kc * 2;
            if (r < N_NODES && c < HC) {
                g_h[(size_t)r * HC + c]     = acc[mi][ni][0];
                g_h[(size_t)r * HC + c + 1] = acc[mi][ni][1];
            }
            if (r + 8 < N_NODES && c < HC) {
                g_h[(size_t)(r + 8) * HC + c]     = acc[mi][ni][2];
                g_h[(size_t)(r + 8) * HC + c + 1] = acc[mi][ni][3];
            }
        }
    }
}

// ---------------- per-node attention scores ----------------------------------
__global__ void k_scores(const float* __restrict__ a_s, const float* __restrict__ a_d) {
    int gwarp = (blockIdx.x * blockDim.x + threadIdx.x) >> 5;
    int lane = threadIdx.x & 31;
    if (gwarp >= N_NODES) return;
    const float* hr = g_h + (size_t)gwarp * HC;
    float s0s = 0.f, s1s = 0.f, s0d = 0.f, s1d = 0.f;
#pragma unroll
    for (int k = 0; k < 7; k++) {
        int c = lane + 32 * k;
        if (c < HC) {
            float v = hr[c];
            float vs = v * a_s[c], vd = v * a_d[c];
            if (c < C_CH) { s0s += vs; s0d += vd; }
            else          { s1s += vs; s1d += vd; }
        }
    }
#pragma unroll
    for (int off = 16; off; off >>= 1) {
        s0s += __shfl_xor_sync(0xffffffffu, s0s, off);
        s1s += __shfl_xor_sync(0xffffffffu, s1s, off);
        s0d += __shfl_xor_sync(0xffffffffu, s0d, off);
        s1d += __shfl_xor_sync(0xffffffffu, s1d, off);
    }
    if (lane == 0) {
        g_es[gwarp * 2 + 0] = s0s; g_es[gwarp * 2 + 1] = s1s;
        g_ed[gwarp * 2 + 0] = s0d; g_ed[gwarp * 2 + 1] = s1d;
    }
}

__device__ __forceinline__ float lrelu(float v) { return v >= 0.f ? v : SLOPE * v; }

// ---------------- warp-per-dst softmax + aggregate + bias + relu -------------
__global__ void k_aggregate(const float* __restrict__ bias) {
    int n = (blockIdx.x * blockDim.x + threadIdx.x) >> 5;
    int lane = threadIdx.x & 31;
    if (n >= N_NODES) return;
    int beg = g_rowptr[n], end = g_rowptr[n + 1];
    float ed0 = g_ed[n * 2 + 0], ed1 = g_ed[n * 2 + 1];

    float m0 = -1e30f, m1 = -1e30f;
    for (int i = beg + lane; i < end; i += 32) {
        int s = g_colsrc[i];
        m0 = fmaxf(m0, lrelu(g_es[s * 2 + 0] + ed0));
        m1 = fmaxf(m1, lrelu(g_es[s * 2 + 1] + ed1));
    }
#pragma unroll
    for (int off = 16; off; off >>= 1) {
        m0 = fmaxf(m0, __shfl_xor_sync(0xffffffffu, m0, off));
        m1 = fmaxf(m1, __shfl_xor_sync(0xffffffffu, m1, off));
    }

    float s0 = 0.f, s1 = 0.f;
    for (int i = beg + lane; i < end; i += 32) {
        int s = g_colsrc[i];
        s0 += __expf(lrelu(g_es[s * 2 + 0] + ed0) - m0);
        s1 += __expf(lrelu(g_es[s * 2 + 1] + ed1) - m1);
    }
#pragma unroll
    for (int off = 16; off; off >>= 1) {
        s0 += __shfl_xor_sync(0xffffffffu, s0, off);
        s1 += __shfl_xor_sync(0xffffffffu, s1, off);
    }
    float inv0 = 1.f / (s0 + 1e-16f), inv1 = 1.f / (s1 + 1e-16f);

    float acc[7];
#pragma unroll
    for (int k = 0; k < 7; k++) acc[k] = 0.f;

    for (int i = beg; i < end; i++) {
        int s = g_colsrc[i];
        float a0 = __expf(lrelu(g_es[s * 2 + 0] + ed0) - m0) * inv0;
        float a1 = __expf(lrelu(g_es[s * 2 + 1] + ed1) - m1) * inv1;
        const float* hr = g_h + (size_t)s * HC;
#pragma unroll
        for (int k = 0; k < 7; k++) {
            int c = lane + 32 * k;
            if (c < HC) acc[k] += (c < C_CH ? a0 : a1) * hr[c];
        }
    }
#pragma unroll
    for (int k = 0; k < 7; k++) {
        int c = lane + 32 * k;
        if (c < HC) {
            float v = acc[k] + bias[c];
            g_x[(size_t)n * HC + c] = v > 0.f ? v : 0.f;
        }
    }
}

// ---------------- global mean pool (batch sorted -> segment reduce) ----------
__global__ void k_pool_seg(const int* __restrict__ batch) {
    int g = blockIdx.x;
    int t = threadIdx.x;
    int lo = 0, hi = N_NODES;
    while (lo < hi) { int m = (lo + hi) >> 1; if (batch[m] < g) lo = m + 1; else hi = m; }
    int beg = lo;
    hi = N_NODES;
    while (lo < hi) { int m = (lo + hi) >> 1; if (batch[m] < g + 1) lo = m + 1; else hi = m; }
    int end = lo;
    float inv = 1.f / fmaxf((float)(end - beg), 1.f);
    for (int c = t; c < HC; c += blockDim.x) {
        float s = 0.f;
        for (int n = beg; n < end; n++) s += g_x[(size_t)n * HC + c];
        g_pool[g * HC + c] = s * inv;
    }
}

// ---------------- fused MLP head ---------------------------------------------
__global__ void k_mlp(const float* __restrict__ lw1, const float* __restrict__ lb1,
                      const float* __restrict__ lw2, const float* __restrict__ lb2,
                      const float* __restrict__ lw3, const float* __restrict__ lb3,
                      float* __restrict__ out) {
    int g = blockIdx.x;
    int t = threadIdx.x;
    __shared__ float buf[HC];
    __shared__ float t1[100];
    __shared__ float t2[100];
    for (int k = t; k < HC; k += blockDim.x) buf[k] = g_pool[g * HC + k];
    __syncthreads();
    if (t < 100) {
        float s = lb1[t];
        for (int k = 0; k < HC; k++) s += buf[k] * lw1[k * 100 + t];
        t1[t] = fmaxf(s, 0.f);
    }
    __syncthreads();
    if (t < 100) {
        float s = lb2[t];
        for (int k = 0; k < 100; k++) s += t1[k] * lw2[k * 100 + t];
        t2[t] = fmaxf(s, 0.f);
    }
    __syncthreads();
    if (t < 29) {
        float s = lb3[t];
        for (int k = 0; k < 100; k++) s += t2[k] * lw3[k * 29 + t];
        out[g * 29 + t] = s;
    }
}

// ---------------- launch ------------------------------------------------------
extern "C" void kernel_launch(void* const* d_in, const int* in_sizes, int n_in,
                              void* d_out, int out_size) {
    const float* x     = (const float*)d_in[0];
    const int*   ei    = (const int*)d_in[1];
    const int*   batch = (const int*)d_in[2];
    const float* W[5];
    const float* Asr[5];
    const float* Ads[5];
    const float* Bc[5];
    for (int i = 0; i < 5; i++) {
        W[i]   = (const float*)d_in[3 + 4 * i];
        Asr[i] = (const float*)d_in[4 + 4 * i];
        Ads[i] = (const float*)d_in[5 + 4 * i];
        Bc[i]  = (const float*)d_in[6 + 4 * i];
    }
    const float* lw1 = (const float*)d_in[23];
    const float* lb1 = (const float*)d_in[24];
    const float* lw2 = (const float*)d_in[25];
    const float* lb2 = (const float*)d_in[26];
    const float* lw3 = (const float*)d_in[27];
    const float* lb3 = (const float*)d_in[28];
    float* out = (float*)d_out;

    k_init_counts<<<(N_NODES + 255) / 256, 256>>>();
    k_count<<<(N_EDGES + 255) / 256, 256>>>(ei);
    k_scan<<<1, 1024>>>();
    k_selfloop<<<(N_NODES + 255) / 256, 256>>>();
    k_fill<<<(N_EDGES + 255) / 256, 256>>>(ei);

    int Kdims[5] = {336, 200, 200, 200, 200};
    int wblocks = (N_NODES + 7) / 8;
    dim3 gemmGrid(4, (N_NODES + 127) / 128);

    // x -> g_x so layer 0 reads the same buffer (device-to-device copy allowed)
    // layer 0 converts directly from x instead to avoid the copy.
    for (int L = 0; L < 5; L++) {
        int K = Kdims[L];
        int KS = K / 8;
        int totA = TM_TILES * KS * 32;
        int totB = TN_TILES * KS * 32;
        const float* Aptr = (L == 0) ? x : nullptr;   // nullptr -> g_x inside? can't; pass g_x
        // we cannot take address of __device__ g_x on host; use flag kernels instead:
        if (L == 0) {
            k_convA<<<(totA + 255) / 256, 256>>>(x, K, KS, totA);
        } else {
            // small trampoline: conversion kernel reading g_x
            // reuse k_convA by passing a device pointer obtained via a helper kernel is
            // not possible here; instead k_convA_gx duplicates the logic.
            extern __global__ void k_convA_gx(int K, int KS, int total);
            k_convA_gx<<<(totA + 255) / 256, 256>>>(K, KS, totA);
        }
        k_convB<<<(totB + 255) / 256, 256>>>(W[L], K, KS, totB);
        k_gemm_tc<<<gemmGrid, 256>>>(KS);
        k_scores<<<wblocks, 256>>>(Asr[L], Ads[L]);
        k_aggregate<<<wblocks, 256>>>(Bc[L]);
    }
    k_pool_seg<<<G_GRAPHS, 256>>>(batch);
    k_mlp<<<G_GRAPHS, 128>>>(lw1, lb1, lw2, lb2, lw3, lb3, out);
}

// conversion from the internal activation buffer g_x
__global__ void k_convA_gx(int K, int KS, int total) {
    int t = blockIdx.x * blockDim.x + threadIdx.x;
    if (t >= total) return;
    int lane = t & 31;
    int rest = t >> 5;
    int ks = rest % KS;
    int tm = rest / KS;
    int groupr = lane >> 2, kc = lane & 3;
    int r0 = tm * 16 + groupr, r1 = r0 + 8;
    int k0 = ks * 8 + kc, k1 = k0 + 4;
    float v0 = g_x[(size_t)r0 * K + k0];
    float v1 = g_x[(size_t)r1 * K + k0];
    float v2 = g_x[(size_t)r0 * K + k1];
    float v3 = g_x[(size_t)r1 * K + k1];
    float h0 = tf32_rna(v0), h1 = tf32_rna(v1), h2 = tf32_rna(v2), h3 = tf32_rna(v3);
    ((float4*)g_pah)[t] = make_float4(h0, h1, h2, h3);
    ((float4*)g_pal)[t] = make_float4(tf32_rna(v0 - h0), tf32_rna(v1 - h1),
                                      tf32_rna(v2 - h2), tf32_rna(v3 - h3));
}

// round 4
// speedup vs baseline: 1.9455x; 1.5091x over previous
#include <cuda_runtime.h>
#include <cuda_bf16.h>
#include <cstdint>

#define N_NODES 50000
#define N_EDGES 400000
#define E_TOT   (N_EDGES + N_NODES)
#define G_GRAPHS 256
#define HC 200
#define C_CH 100
#define SLOPE 0.2f

#define TM_TILES 3125          // 50000 / 16 (exact)
#define TN_TILES 25            // 200 / 8 (exact)
#define KS16_MAX 21            // 336 / 16
#define NB_SCAN 196            // ceil(50000/256)

// ---------------- scratch (device globals; no allocation allowed) ------------
__device__ float g_h[(size_t)N_NODES * HC];
__device__ float g_x[(size_t)N_NODES * HC];
__device__ float g_es[N_NODES * 2];
__device__ float g_ed[N_NODES * 2];
__device__ int   g_rowptr[N_NODES + 1];
__device__ int   g_cnt[N_NODES];
__device__ int   g_fill[N_NODES];
__device__ int   g_colsrc[E_TOT];
__device__ float g_pool[G_GRAPHS * HC];
__device__ int   g_bsum[256];
__device__ int   g_boff[256];
// permuted bf16 hi/lo operands in exact mma.m16n8k16 fragment order
__device__ uint4 g_pah[(size_t)TM_TILES * KS16_MAX * 32];
__device__ uint4 g_pal[(size_t)TM_TILES * KS16_MAX * 32];
__device__ uint2 g_pbh[(size_t)TN_TILES * KS16_MAX * 32];
__device__ uint2 g_pbl[(size_t)TN_TILES * KS16_MAX * 32];

// ---------------- CSR build --------------------------------------------------
__global__ void k_init_counts() {
    int i = blockIdx.x * blockDim.x + threadIdx.x;
    if (i < N_NODES) { g_cnt[i] = 1; g_fill[i] = 1; }
}

__global__ void k_count(const int* __restrict__ ei) {
    int e = blockIdx.x * blockDim.x + threadIdx.x;
    if (e < N_EDGES) atomicAdd(&g_cnt[ei[N_EDGES + e]], 1);
}

// two-level scan: per-block inclusive scan + block sums
__global__ void k_scan1() {
    __shared__ int ws[8];
    int b = blockIdx.x, t = threadIdx.x;
    int i = b * 256 + t;
    int lane = t & 31, w = t >> 5;
    int v = (i < N_NODES) ? g_cnt[i] : 0;
    int s = v;
#pragma unroll
    for (int off = 1; off < 32; off <<= 1) {
        int u = __shfl_up_sync(0xffffffffu, s, off);
        if (lane >= off) s += u;
    }
    if (lane == 31) ws[w] = s;
    __syncthreads();
    if (t == 0) {
        int run = 0;
#pragma unroll
        for (int j = 0; j < 8; j++) { int tmp = ws[j]; ws[j] = run; run += tmp; }
        g_bsum[b] = run;
    }
    __syncthreads();
    if (i < N_NODES) g_rowptr[i + 1] = s + ws[w];
}

__global__ void k_scan2() {
    __shared__ int ws[8];
    int t = threadIdx.x;
    int lane = t & 31, w = t >> 5;
    int v = (t < NB_SCAN) ? g_bsum[t] : 0;
    int s = v;
#pragma unroll
    for (int off = 1; off < 32; off <<= 1) {
        int u = __shfl_up_sync(0xffffffffu, s, off);
        if (lane >= off) s += u;
    }
    if (lane == 31) ws[w] = s;
    __syncthreads();
    if (t == 0) {
        int run = 0;
#pragma unroll
        for (int j = 0; j < 8; j++) { int tmp = ws[j]; ws[j] = run; run += tmp; }
    }
    __syncthreads();
    if (t < NB_SCAN) g_boff[t] = s + ws[w] - v;   // exclusive
}

__global__ void k_scan3() {
    int i = blockIdx.x * blockDim.x + threadIdx.x;
    if (i == 0) g_rowptr[0] = 0;
    if (i < N_NODES) g_rowptr[i + 1] += g_boff[i >> 8];
}

__global__ void k_selfloop() {
    int i = blockIdx.x * blockDim.x + threadIdx.x;
    if (i < N_NODES) g_colsrc[g_rowptr[i]] = i;
}

__global__ void k_fill(const int* __restrict__ ei) {
    int e = blockIdx.x * blockDim.x + threadIdx.x;
    if (e < N_EDGES) {
        int d = ei[N_EDGES + e];
        int pos = g_rowptr[d] + atomicAdd(&g_fill[d], 1);
        g_colsrc[pos] = ei[e];
    }
}

// ---------------- bf16 helpers -----------------------------------------------
__device__ __forceinline__ uint32_t packbf(float a, float b) {
    __nv_bfloat162 p = __floats2bfloat162_rn(a, b);   // a -> low half
    return *(uint32_t*)&p;
}
__device__ __forceinline__ float bfhi(float v) {
    return __bfloat162float(__float2bfloat16_rn(v));
}

__device__ __forceinline__ void mma_bf16(float& c0, float& c1, float& c2, float& c3,
                                         uint32_t a0, uint32_t a1, uint32_t a2, uint32_t a3,
                                         uint32_t b0, uint32_t b1) {
    asm volatile(
        "mma.sync.aligned.m16n8k16.row.col.f32.bf16.bf16.f32 "
        "{%0,%1,%2,%3},{%4,%5,%6,%7},{%8,%9},{%0,%1,%2,%3};"
        : "+f"(c0), "+f"(c1), "+f"(c2), "+f"(c3)
        : "r"(a0), "r"(a1), "r"(a2), "r"(a3), "r"(b0), "r"(b1));
}

// ---------------- operand pre-permute + hi/lo bf16 split ---------------------
// A fragment (m16n8k16): a0={A[r0][2kc],A[r0][2kc+1]}, a1=row r0+8 same cols,
//                        a2={A[r0][2kc+8],+9}, a3=row r0+8 cols +8,+9
__device__ __forceinline__ void convA_body(const float* __restrict__ A, int K, int KS, int t) {
    int lane = t & 31;
    int rest = t >> 5;
    int ks = rest % KS;
    int tm = rest / KS;
    int groupr = lane >> 2, kc = lane & 3;
    int r0 = tm * 16 + groupr, r1 = r0 + 8;
    int k0 = ks * 16 + kc * 2;
    float v[2][4];   // [row][col: k0,k0+1,k0+8,k0+9]
    const float* p0 = A + (size_t)r0 * K;
    const float* p1 = A + (size_t)r1 * K;
#pragma unroll
    for (int j = 0; j < 4; j++) {
        int k = k0 + (j >> 1) * 8 + (j & 1);
        v[0][j] = (k < K) ? p0[k] : 0.f;
        v[1][j] = (k < K) ? p1[k] : 0.f;
    }
    float h[2][4], l[2][4];
#pragma unroll
    for (int r = 0; r < 2; r++)
#pragma unroll
        for (int j = 0; j < 4; j++) { h[r][j] = bfhi(v[r][j]); l[r][j] = v[r][j] - h[r][j]; }
    g_pah[t] = make_uint4(packbf(h[0][0], h[0][1]), packbf(h[1][0], h[1][1]),
                          packbf(h[0][2], h[0][3]), packbf(h[1][2], h[1][3]));
    g_pal[t] = make_uint4(packbf(l[0][0], l[0][1]), packbf(l[1][0], l[1][1]),
                          packbf(l[0][2], l[0][3]), packbf(l[1][2], l[1][3]));
}

__global__ void k_convA(const float* __restrict__ A, int K, int KS, int total) {
    int t = blockIdx.x * blockDim.x + threadIdx.x;
    if (t < total) convA_body(A, K, KS, t);
}
__global__ void k_convA_gx(int K, int KS, int total) {
    int t = blockIdx.x * blockDim.x + threadIdx.x;
    if (t < total) convA_body(g_x, K, KS, t);
}

// B fragment: b0={B[k0][n],B[k0+1][n]}, b1={B[k0+8][n],B[k0+9][n]}; n=tn*8+groupr
__global__ void k_convB(const float* __restrict__ B, int K, int KS, int total) {
    int t = blockIdx.x * blockDim.x + threadIdx.x;
    if (t >= total) return;
    int lane = t & 31;
    int rest = t >> 5;
    int ks = rest % KS;
    int tn = rest / KS;
    int groupr = lane >> 2, kc = lane & 3;
    int n = tn * 8 + groupr;
    int k0 = ks * 16 + kc * 2;
    float v[4];
#pragma unroll
    for (int j = 0; j < 4; j++) {
        int k = k0 + (j >> 1) * 8 + (j & 1);
        v[j] = (k < K) ? B[(size_t)k * HC + n] : 0.f;
    }
    float h[4], l[4];
#pragma unroll
    for (int j = 0; j < 4; j++) { h[j] = bfhi(v[j]); l[j] = v[j] - h[j]; }
    g_pbh[t] = make_uint2(packbf(h[0], h[1]), packbf(h[2], h[3]));
    g_pbl[t] = make_uint2(packbf(l[0], l[1]), packbf(l[2], l[3]));
}

// ---------------- smem-free bf16x3 tensor-core GEMM --------------------------
// block = 8 warps (4m x 2n), warp tile 32m x 32n -> 2x4 m16n8k16 tiles.
__global__ void __launch_bounds__(256)
k_gemm_tc(int KS) {
    int tid = threadIdx.x;
    int lane = tid & 31, warp = tid >> 5;
    int wm = warp & 3, wn = warp >> 2;
    int tm0 = blockIdx.y * 8 + wm * 2;
    int tnB = blockIdx.x * 8 + wn * 4;
    if (tnB >= TN_TILES) return;

    bool mv0 = tm0 < TM_TILES;
    bool mv1 = (tm0 + 1) < TM_TILES;
    bool nv[4];
#pragma unroll
    for (int ni = 0; ni < 4; ni++) nv[ni] = (tnB + ni) < TN_TILES;

    size_t aBase0 = ((size_t)tm0 * KS) * 32 + lane;
    size_t aBase1 = aBase0 + (size_t)KS * 32;
    size_t bBase[4];
#pragma unroll
    for (int ni = 0; ni < 4; ni++) bBase[ni] = ((size_t)(tnB + ni) * KS) * 32 + lane;

    float acc[2][4][4];
#pragma unroll
    for (int mi = 0; mi < 2; mi++)
#pragma unroll
        for (int ni = 0; ni < 4; ni++)
#pragma unroll
            for (int r = 0; r < 4; r++) acc[mi][ni][r] = 0.f;

    const uint4 z4 = make_uint4(0, 0, 0, 0);
    const uint2 z2 = make_uint2(0, 0);

#pragma unroll 2
    for (int ks = 0; ks < KS; ks++) {
        size_t off = (size_t)ks * 32;
        uint4 ah0 = mv0 ? g_pah[aBase0 + off] : z4;
        uint4 al0 = mv0 ? g_pal[aBase0 + off] : z4;
        uint4 ah1 = mv1 ? g_pah[aBase1 + off] : z4;
        uint4 al1 = mv1 ? g_pal[aBase1 + off] : z4;
        uint2 bh[4], bl[4];
#pragma unroll
        for (int ni = 0; ni < 4; ni++) {
            bh[ni] = nv[ni] ? g_pbh[bBase[ni] + off] : z2;
            bl[ni] = nv[ni] ? g_pbl[bBase[ni] + off] : z2;
        }
#pragma unroll
        for (int ni = 0; ni < 4; ni++) {
            {
                float* c = acc[0][ni];
                mma_bf16(c[0], c[1], c[2], c[3], ah0.x, ah0.y, ah0.z, ah0.w, bh[ni].x, bh[ni].y);
                mma_bf16(c[0], c[1], c[2], c[3], al0.x, al0.y, al0.z, al0.w, bh[ni].x, bh[ni].y);
                mma_bf16(c[0], c[1], c[2], c[3], ah0.x, ah0.y, ah0.z, ah0.w, bl[ni].x, bl[ni].y);
            }
            {
                float* c = acc[1][ni];
                mma_bf16(c[0], c[1], c[2], c[3], ah1.x, ah1.y, ah1.z, ah1.w, bh[ni].x, bh[ni].y);
                mma_bf16(c[0], c[1], c[2], c[3], al1.x, al1.y, al1.z, al1.w, bh[ni].x, bh[ni].y);
                mma_bf16(c[0], c[1], c[2], c[3], ah1.x, ah1.y, ah1.z, ah1.w, bl[ni].x, bl[ni].y);
            }
        }
    }

    int groupr = lane >> 2, kc = lane & 3;
#pragma unroll
    for (int mi = 0; mi < 2; mi++) {
        if (!(mi ? mv1 : mv0)) continue;
        int r = (tm0 + mi) * 16 + groupr;
#pragma unroll
        for (int ni = 0; ni < 4; ni++) {
            if (!nv[ni]) continue;
            int c = (tnB + ni) * 8 + kc * 2;
            g_h[(size_t)r * HC + c]           = acc[mi][ni][0];
            g_h[(size_t)r * HC + c + 1]       = acc[mi][ni][1];
            g_h[(size_t)(r + 8) * HC + c]     = acc[mi][ni][2];
            g_h[(size_t)(r + 8) * HC + c + 1] = acc[mi][ni][3];
        }
    }
}

// ---------------- per-node attention scores ----------------------------------
__global__ void k_scores(const float* __restrict__ a_s, const float* __restrict__ a_d) {
    int gwarp = (blockIdx.x * blockDim.x + threadIdx.x) >> 5;
    int lane = threadIdx.x & 31;
    if (gwarp >= N_NODES) return;
    const float* hr = g_h + (size_t)gwarp * HC;
    float s0s = 0.f, s1s = 0.f, s0d = 0.f, s1d = 0.f;
#pragma unroll
    for (int k = 0; k < 7; k++) {
        int c = lane + 32 * k;
        if (c < HC) {
            float v = hr[c];
            float vs = v * a_s[c], vd = v * a_d[c];
            if (c < C_CH) { s0s += vs; s0d += vd; }
            else          { s1s += vs; s1d += vd; }
        }
    }
#pragma unroll
    for (int off = 16; off; off >>= 1) {
        s0s += __shfl_xor_sync(0xffffffffu, s0s, off);
        s1s += __shfl_xor_sync(0xffffffffu, s1s, off);
        s0d += __shfl_xor_sync(0xffffffffu, s0d, off);
        s1d += __shfl_xor_sync(0xffffffffu, s1d, off);
    }
    if (lane == 0) {
        g_es[gwarp * 2 + 0] = s0s; g_es[gwarp * 2 + 1] = s1s;
        g_ed[gwarp * 2 + 0] = s0d; g_ed[gwarp * 2 + 1] = s1d;
    }
}

__device__ __forceinline__ float lrelu(float v) { return v >= 0.f ? v : SLOPE * v; }

// ---------------- warp-per-dst softmax + aggregate + bias + relu -------------
__global__ void k_aggregate(const float* __restrict__ bias) {
    int n = (blockIdx.x * blockDim.x + threadIdx.x) >> 5;
    int lane = threadIdx.x & 31;
    if (n >= N_NODES) return;
    int beg = g_rowptr[n], end = g_rowptr[n + 1];
    float ed0 = g_ed[n * 2 + 0], ed1 = g_ed[n * 2 + 1];

    float m0 = -1e30f, m1 = -1e30f;
    for (int i = beg + lane; i < end; i += 32) {
        int s = g_colsrc[i];
        m0 = fmaxf(m0, lrelu(g_es[s * 2 + 0] + ed0));
        m1 = fmaxf(m1, lrelu(g_es[s * 2 + 1] + ed1));
    }
#pragma unroll
    for (int off = 16; off; off >>= 1) {
        m0 = fmaxf(m0, __shfl_xor_sync(0xffffffffu, m0, off));
        m1 = fmaxf(m1, __shfl_xor_sync(0xffffffffu, m1, off));
    }

    float s0 = 0.f, s1 = 0.f;
    for (int i = beg + lane; i < end; i += 32) {
        int s = g_colsrc[i];
        s0 += __expf(lrelu(g_es[s * 2 + 0] + ed0) - m0);
        s1 += __expf(lrelu(g_es[s * 2 + 1] + ed1) - m1);
    }
#pragma unroll
    for (int off = 16; off; off >>= 1) {
        s0 += __shfl_xor_sync(0xffffffffu, s0, off);
        s1 += __shfl_xor_sync(0xffffffffu, s1, off);
    }
    float inv0 = 1.f / (s0 + 1e-16f), inv1 = 1.f / (s1 + 1e-16f);

    float acc[7];
#pragma unroll
    for (int k = 0; k < 7; k++) acc[k] = 0.f;

    for (int i = beg; i < end; i++) {
        int s = g_colsrc[i];
        float a0 = __expf(lrelu(g_es[s * 2 + 0] + ed0) - m0) * inv0;
        float a1 = __expf(lrelu(g_es[s * 2 + 1] + ed1) - m1) * inv1;
        const float* hr = g_h + (size_t)s * HC;
#pragma unroll
        for (int k = 0; k < 7; k++) {
            int c = lane + 32 * k;
            if (c < HC) acc[k] += (c < C_CH ? a0 : a1) * hr[c];
        }
    }
#pragma unroll
    for (int k = 0; k < 7; k++) {
        int c = lane + 32 * k;
        if (c < HC) {
            float v = acc[k] + bias[c];
            g_x[(size_t)n * HC + c] = v > 0.f ? v : 0.f;
        }
    }
}

// ---------------- global mean pool (batch sorted -> segment reduce) ----------
__global__ void k_pool_seg(const int* __restrict__ batch) {
    int g = blockIdx.x;
    int t = threadIdx.x;
    int lo = 0, hi = N_NODES;
    while (lo < hi) { int m = (lo + hi) >> 1; if (batch[m] < g) lo = m + 1; else hi = m; }
    int beg = lo;
    hi = N_NODES;
    while (lo < hi) { int m = (lo + hi) >> 1; if (batch[m] < g + 1) lo = m + 1; else hi = m; }
    int end = lo;
    float inv = 1.f / fmaxf((float)(end - beg), 1.f);
    for (int c = t; c < HC; c += blockDim.x) {
        float s = 0.f;
        for (int n = beg; n < end; n++) s += g_x[(size_t)n * HC + c];
        g_pool[g * HC + c] = s * inv;
    }
}

// ---------------- fused MLP head ---------------------------------------------
__global__ void k_mlp(const float* __restrict__ lw1, const float* __restrict__ lb1,
                      const float* __restrict__ lw2, const float* __restrict__ lb2,
                      const float* __restrict__ lw3, const float* __restrict__ lb3,
                      float* __restrict__ out) {
    int g = blockIdx.x;
    int t = threadIdx.x;
    __shared__ float buf[HC];
    __shared__ float t1[100];
    __shared__ float t2[100];
    for (int k = t; k < HC; k += blockDim.x) buf[k] = g_pool[g * HC + k];
    __syncthreads();
    if (t < 100) {
        float s = lb1[t];
        for (int k = 0; k < HC; k++) s += buf[k] * lw1[k * 100 + t];
        t1[t] = fmaxf(s, 0.f);
    }
    __syncthreads();
    if (t < 100) {
        float s = lb2[t];
        for (int k = 0; k < 100; k++) s += t1[k] * lw2[k * 100 + t];
        t2[t] = fmaxf(s, 0.f);
    }
    __syncthreads();
    if (t < 29) {
        float s = lb3[t];
        for (int k = 0; k < 100; k++) s += t2[k] * lw3[k * 29 + t];
        out[g * 29 + t] = s;
    }
}

// ---------------- launch ------------------------------------------------------
extern "C" void kernel_launch(void* const* d_in, const int* in_sizes, int n_in,
                              void* d_out, int out_size) {
    const float* x     = (const float*)d_in[0];
    const int*   ei    = (const int*)d_in[1];
    const int*   batch = (const int*)d_in[2];
    const float* W[5];
    const float* Asr[5];
    const float* Ads[5];
    const float* Bc[5];
    for (int i = 0; i < 5; i++) {
        W[i]   = (const float*)d_in[3 + 4 * i];
        Asr[i] = (const float*)d_in[4 + 4 * i];
        Ads[i] = (const float*)d_in[5 + 4 * i];
        Bc[i]  = (const float*)d_in[6 + 4 * i];
    }
    const float* lw1 = (const float*)d_in[23];
    const float* lb1 = (const float*)d_in[24];
    const float* lw2 = (const float*)d_in[25];
    const float* lb2 = (const float*)d_in[26];
    const float* lw3 = (const float*)d_in[27];
    const float* lb3 = (const float*)d_in[28];
    float* out = (float*)d_out;

    k_init_counts<<<(N_NODES + 255) / 256, 256>>>();
    k_count<<<(N_EDGES + 255) / 256, 256>>>(ei);
    k_scan1<<<NB_SCAN, 256>>>();
    k_scan2<<<1, 256>>>();
    k_scan3<<<(N_NODES + 255) / 256, 256>>>();
    k_selfloop<<<(N_NODES + 255) / 256, 256>>>();
    k_fill<<<(N_EDGES + 255) / 256, 256>>>(ei);

    int Kdims[5] = {336, 200, 200, 200, 200};
    int wblocks = (N_NODES + 7) / 8;
    dim3 gemmGrid(4, (TM_TILES + 7) / 8);

    for (int L = 0; L < 5; L++) {
        int K = Kdims[L];
        int KS = (K + 15) / 16;
        int totA = TM_TILES * KS * 32;
        int totB = TN_TILES * KS * 32;
        if (L == 0) k_convA<<<(totA + 255) / 256, 256>>>(x, K, KS, totA);
        else        k_convA_gx<<<(totA + 255) / 256, 256>>>(K, KS, totA);
        k_convB<<<(totB + 255) / 256, 256>>>(W[L], K, KS, totB);
        k_gemm_tc<<<gemmGrid, 256>>>(KS);
        k_scores<<<wblocks, 256>>>(Asr[L], Ads[L]);
        k_aggregate<<<wblocks, 256>>>(Bc[L]);
    }
    k_pool_seg<<<G_GRAPHS, 256>>>(batch);
    k_mlp<<<G_GRAPHS, 128>>>(lw1, lb1, lw2, lb2, lw3, lb3, out);
}